// round 14
// baseline (speedup 1.0000x reference)
#include <cuda_runtime.h>
#include <cuda_fp16.h>
#include <math.h>
#include <stdint.h>

#define BB 4
#define TT 1024
#define DD 1024
#define HH 16
#define DKV 64
#define FFD 4096

#define XL   (BB * TT * DD)            // 4,194,304
#define WL   (DD * DD)                 // 1,048,576
#define SL   ((long)BB * HH * TT * TT) // 67,108,864
#define HIDL ((long)BB * TT * FFD)     // 16,777,216

// ---- single-plane fp16 format (RN) -------------------------------------------------
__device__ __align__(16) __half g_xy  [2 * XL];       // y, x
__device__ __align__(16) __half g_Wt  [6 * WL];       // q/k/v weights both MHAs (transposed)
__device__ __align__(16) __half g_WoT [2 * WL];
__device__ __align__(16) __half g_Win [4 * WL];
__device__ __align__(16) __half g_Wout[4 * WL];
__device__ __align__(16) __half g_QKV [6 * XL];       // QKV for both MHAs
__device__ __align__(16) __half g_Vt  [2 * XL];
__device__ __align__(16) __half g_S   [2 * SL];       // 268 MB
__device__ __align__(16) __half g_P   [2 * XL];
__device__ __align__(16) __half g_hid [HIDL];
__device__ float g_cpart[2 * BB * HH * 8 * TT];       // column partials, both MHAs (4MB)
__device__ float g_dinv [2 * BB * HH * TT];
__device__ float g_M [2 * XL];
__device__ float g_o1[XL];
__device__ float g_o2[XL];
__device__ float g_ff[XL];

// ---- GEMM segment descriptor --------------------------------------------------------
// flags: 1=BIAS, 2=RELU, 4=EXP, 8=PACK(fp16 out), 16=CSUM
struct GDesc {
    const __half* A; const __half* B;
    const float* bias; void* C; float* cpart;
    int K, lda, ldb, ldc;
    long sA1, sA2, sB1, sB2, sC1, sC2;
    int zdiv; float alpha; int gx, gy;
    int flags; int tile_end;
};

// ---------------- helpers ----------------
__device__ __forceinline__ void mma_f16(float* c, const uint32_t* a, const uint32_t* b) {
    asm volatile(
        "mma.sync.aligned.m16n8k16.row.col.f32.f16.f16.f32 "
        "{%0,%1,%2,%3}, {%4,%5,%6,%7}, {%8,%9}, {%0,%1,%2,%3};"
        : "+f"(c[0]), "+f"(c[1]), "+f"(c[2]), "+f"(c[3])
        : "r"(a[0]), "r"(a[1]), "r"(a[2]), "r"(a[3]), "r"(b[0]), "r"(b[1]));
}

// ---------------- multi-segment fp16 GEMM (persistent, templated tile width) ---------
// Tile: 128 x BN of alpha * A[M,K] @ B[N,K]^T. 8 warps (4x2), warp tile 32 x (BN/2).
// 4-stage cp.async, single sync per chunk. PACK epilogue stages the fp16 tile in
// smem (stride BN+8, conflict-free) and emits coalesced STG.128.
template<int BN>
__global__ __launch_bounds__(256, (BN == 64) ? 3 : 2)
void mma_multi(GDesc D0, GDesc D1, GDesc D2, int ntot)
{
    constexpr int NT   = BN / 16;         // n8 tiles per warp
    constexpr int NST  = 4;
    constexpr int STGH = 4096 + BN * 32;  // halves per stage (A + B)
    constexpr int OFF_B = 4096;
    constexpr int NGRP = (128 + BN) * 4;  // 16B groups per stage
    constexpr int EPS  = BN + 8;          // epilogue row stride (halves)

    extern __shared__ __half smh[];
    uint32_t smb;
    asm("{ .reg .u64 t; cvta.to.shared.u64 t, %1; cvt.u32.u64 %0, t; }" : "=r"(smb) : "l"(smh));

    const int tid  = threadIdx.x;
    const int lane = tid & 31;
    const int wid  = tid >> 5;
    const int wm   = wid >> 1;            // 0..3
    const int wn   = wid & 1;             // 0..1
    const int g    = lane >> 2;
    const int tg   = lane & 3;

    const int ar = wm * 32 + g;
    const int br = wn * (BN / 2) + g;

    for (int tile = blockIdx.x; tile < ntot; tile += gridDim.x) {
        const bool in0 = tile < D0.tile_end;
        const bool in1 = tile < D1.tile_end;
        const GDesc d = in0 ? D0 : (in1 ? D1 : D2);
        const int base = in0 ? 0 : (in1 ? D0.tile_end : D1.tile_end);

        const int lt  = tile - base;
        const int z   = lt / (d.gx * d.gy);
        const int rem = lt % (d.gx * d.gy);
        const int trow = rem / d.gx;
        const int row0 = trow * 128;
        const int col0 = (rem % d.gx) * BN;
        const int z1 = z / d.zdiv, z2 = z % d.zdiv;
        const __half* Ahz = d.A + z1 * d.sA1 + z2 * d.sA2;
        const __half* Bhz = d.B + z1 * d.sB1 + z2 * d.sB2;
        const long coff = z1 * d.sC1 + z2 * d.sC2;
        const int lda = d.lda, ldb = d.ldb, ldc = d.ldc;
        const int flags = d.flags;

        float acc[2][NT][4];
        #pragma unroll
        for (int i = 0; i < 2; i++)
            #pragma unroll
            for (int j = 0; j < NT; j++)
                #pragma unroll
                for (int q = 0; q < 4; q++) acc[i][j][q] = 0.f;

        const int nch = d.K / 32;

        auto copy_stage = [&](int s, int c) {
            const int kk = c * 32;
            #pragma unroll
            for (int i = tid; i < NGRP; i += 256) {
                const __half* src;
                uint32_t doff;
                if (i < 512) {
                    int r = i >> 2, q = i & 3;
                    src = Ahz + (long)(row0 + r) * lda + kk + q * 8;
                    doff = (uint32_t)(r * 32 + q * 8);
                } else {
                    int j = i - 512;
                    int r = j >> 2, q = j & 3;
                    src = Bhz + (long)(col0 + r) * ldb + kk + q * 8;
                    doff = (uint32_t)(OFF_B + r * 32 + q * 8);
                }
                uint32_t dst = smb + 2u * ((uint32_t)s * STGH + doff);
                asm volatile("cp.async.cg.shared.global [%0], [%1], 16;" :: "r"(dst), "l"(src));
            }
        };

        // prologue: stages 0..2
        #pragma unroll
        for (int s = 0; s < NST - 1; s++) {
            if (s < nch) copy_stage(s, s);
            asm volatile("cp.async.commit_group;" ::: "memory");
        }

        for (int c = 0; c < nch; c++) {
            asm volatile("cp.async.wait_group %0;" :: "n"(NST - 2) : "memory");
            __syncthreads();   // chunk c ready; also licenses overwrite of stage (c-1)&3
            if (c + NST - 1 < nch) copy_stage((c + NST - 1) & (NST - 1), c + NST - 1);
            asm volatile("cp.async.commit_group;" ::: "memory");

            const __half* St = smh + (c & (NST - 1)) * STGH;

            // A fragments: [mt][ks][4]
            uint32_t Ah[2][2][4];
            #pragma unroll
            for (int mt = 0; mt < 2; mt++) {
                const __half* arow = St + (ar + 16 * mt) * 32 + tg * 8;
                uint4 h0 = *(const uint4*)(arow);
                uint4 h1 = *(const uint4*)(arow + 8 * 32);
                Ah[mt][0][0] = h0.x; Ah[mt][0][1] = h1.x; Ah[mt][0][2] = h0.y; Ah[mt][0][3] = h1.y;
                Ah[mt][1][0] = h0.z; Ah[mt][1][1] = h1.z; Ah[mt][1][2] = h0.w; Ah[mt][1][3] = h1.w;
            }
            #pragma unroll
            for (int nt = 0; nt < NT; nt++) {
                uint4 bv = *(const uint4*)(St + OFF_B + (br + 8 * nt) * 32 + tg * 8);
                uint32_t b0[2] = {bv.x, bv.y};
                uint32_t b1[2] = {bv.z, bv.w};
                #pragma unroll
                for (int mt = 0; mt < 2; mt++) {
                    mma_f16(acc[mt][nt], Ah[mt][0], b0);
                    mma_f16(acc[mt][nt], Ah[mt][1], b1);
                }
            }
        }

        __syncthreads();   // compute done; smem stages dead -> reusable as epi buffer

        const float alpha = d.alpha;
        float cs[NT][2];
        #pragma unroll
        for (int nt = 0; nt < NT; nt++) { cs[nt][0] = 0.f; cs[nt][1] = 0.f; }

        if (flags & 8) {
            // -------- staged fp16 epilogue -> coalesced STG.128
            __half* eb = smh;                         // 128 x EPS halves
            float* colpart = (float*)(smh + 128 * EPS);
            #pragma unroll
            for (int mt = 0; mt < 2; mt++) {
                #pragma unroll
                for (int half_ = 0; half_ < 2; half_++) {
                    const int er = wm * 32 + mt * 16 + half_ * 8 + g;
                    #pragma unroll
                    for (int nt = 0; nt < NT; nt++) {
                        const int ec = wn * (BN / 2) + tg * 2 + nt * 8;
                        float v0 = acc[mt][nt][half_ * 2 + 0] * alpha;
                        float v1 = acc[mt][nt][half_ * 2 + 1] * alpha;
                        if (flags & 4)  { v0 = __expf(v0); v1 = __expf(v1); }
                        if (flags & 1)  { v0 += d.bias[col0 + ec]; v1 += d.bias[col0 + ec + 1]; }
                        if (flags & 2)  { v0 = fmaxf(v0, 0.f); v1 = fmaxf(v1, 0.f); }
                        if (flags & 16) { cs[nt][0] += v0; cs[nt][1] += v1; }
                        *(__half2*)(eb + er * EPS + ec) =
                            __halves2half2(__float2half_rn(v0), __float2half_rn(v1));
                    }
                }
            }
            if (flags & 16) {
                #pragma unroll
                for (int nt = 0; nt < NT; nt++) {
                    #pragma unroll
                    for (int p = 0; p < 2; p++) {
                        float v = cs[nt][p];
                        v += __shfl_xor_sync(0xffffffffu, v, 4);
                        v += __shfl_xor_sync(0xffffffffu, v, 8);
                        v += __shfl_xor_sync(0xffffffffu, v, 16);
                        cs[nt][p] = v;
                    }
                }
                if (g == 0) {
                    #pragma unroll
                    for (int nt = 0; nt < NT; nt++) {
                        int lc = wn * (BN / 2) + tg * 2 + nt * 8;
                        colpart[wm * BN + lc]     = cs[nt][0];
                        colpart[wm * BN + lc + 1] = cs[nt][1];
                    }
                }
            }
            __syncthreads();
            // coalesced copy: 128*BN/8 uint4, BN/16 per thread
            __half* Ch = (__half*)d.C;
            const long crow0 = coff + (long)row0 * ldc + col0;
            #pragma unroll
            for (int k = 0; k < BN / 16; k++) {
                int j = tid + k * 256;
                int r = j / (BN / 8), u = j % (BN / 8);
                uint4 v = *(const uint4*)(eb + r * EPS + u * 8);
                *(uint4*)(Ch + crow0 + (long)r * ldc + u * 8) = v;
            }
            if ((flags & 16) && tid < BN) {
                float s4 = colpart[tid] + colpart[BN + tid] +
                           colpart[2 * BN + tid] + colpart[3 * BN + tid];
                d.cpart[(long)z * 8192 + trow * 1024 + col0 + tid] = s4;
            }
        } else {
            // -------- fp32 direct epilogue (M, ff)
            float* Cf = (float*)d.C;
            const int rbase = row0 + wm * 32 + g;
            const int cbase = col0 + wn * (BN / 2) + tg * 2;
            #pragma unroll
            for (int mt = 0; mt < 2; mt++) {
                #pragma unroll
                for (int half_ = 0; half_ < 2; half_++) {
                    const long gm = rbase + mt * 16 + half_ * 8;
                    const long rowoff = coff + gm * ldc;
                    #pragma unroll
                    for (int nt = 0; nt < NT; nt++) {
                        const int gn = cbase + nt * 8;
                        float v0 = acc[mt][nt][half_ * 2 + 0] * alpha;
                        float v1 = acc[mt][nt][half_ * 2 + 1] * alpha;
                        if (flags & 1) { v0 += d.bias[gn]; v1 += d.bias[gn + 1]; }
                        float2 o; o.x = v0; o.y = v1;
                        *(float2*)(Cf + rowoff + gn) = o;
                    }
                }
            }
        }
        __syncthreads();   // epi buffer / stages safe before next tile's prologue
    }
}

// -------- convert pass: fp32 -> fp16 (RN) --------------------------------------------
__global__ void split_pairs(const float* __restrict__ in, __half* __restrict__ out,
                            int npairs) {
    int i = blockIdx.x * 256 + threadIdx.x;
    if (i >= npairs) return;
    float2 v = *(const float2*)(in + 2 * i);
    *(__half2*)(out + 2 * i) = __halves2half2(__float2half_rn(v.x), __float2half_rn(v.y));
}

// -------- dinv from column partials (both MHAs) --------------------------------------
__global__ void inv_partials(const float* __restrict__ cpart, float* __restrict__ dinv) {
    int i = blockIdx.x * 256 + threadIdx.x;     // 131072 total
    int z = i >> 10, s = i & 1023;
    const float* p = cpart + (long)z * 8192 + s;
    float a = 0.f;
    #pragma unroll
    for (int tr = 0; tr < 8; tr++) a += p[tr * 1024];
    dinv[i] = 1.f / a;
}

// -------- transpose: out[z][c][r] = in[z][r][c] (*scale[z][r]); fp16 out -------------
template<bool SC, bool PIN>
__global__ void transpose_pk(const void* __restrict__ inv, __half* __restrict__ out,
                             const float* __restrict__ scale,
                             int R, int ldin, int ldout,
                             long inS1, long inS2, int zdiv)
{
    __shared__ float tile[32][33];
    const int z = blockIdx.z;
    const long inoff = (long)(z / zdiv) * inS1 + (long)(z % zdiv) * inS2;
    const long outz = (long)z * (long)gridDim.x * 32 * ldout;
    const int c0 = blockIdx.x * 32, r0 = blockIdx.y * 32;
    const int tx = threadIdx.x, ty = threadIdx.y;
    #pragma unroll
    for (int i = ty; i < 32; i += 8) {
        float v;
        long idx = (long)(r0 + i) * ldin + c0 + tx;
        if (PIN) v = __half2float(((const __half*)inv + inoff)[idx]);
        else     v = ((const float*)inv + inoff)[idx];
        if (SC) v *= scale[(long)z * R + r0 + i];
        tile[i][tx] = v;
    }
    __syncthreads();
    #pragma unroll
    for (int i = ty; i < 32; i += 8) {
        long o = outz + (long)(c0 + i) * ldout + r0 + tx;
        out[o] = __float2half_rn(tile[tx][i]);
    }
}

// ---------------- reductions + sub_norm ----------------------------------------------
__device__ __forceinline__ float blockReduceSum(float v) {
    __shared__ float sh[32];
    __syncthreads();
    int lane = threadIdx.x & 31, wid = threadIdx.x >> 5;
    #pragma unroll
    for (int o = 16; o; o >>= 1) v += __shfl_xor_sync(0xffffffffu, v, o);
    if (lane == 0) sh[wid] = v;
    __syncthreads();
    if (wid == 0) {
        v = (threadIdx.x < (blockDim.x >> 5)) ? sh[lane] : 0.f;
        #pragma unroll
        for (int o = 16; o; o >>= 1) v += __shfl_xor_sync(0xffffffffu, v, o);
        if (lane == 0) sh[0] = v;
    }
    __syncthreads();
    return sh[0];
}

__global__ void add_subnorm(const float* __restrict__ A, const float* __restrict__ R,
                            float* __restrict__ O) {
    long base = (long)blockIdx.x * 1024;
    int t = threadIdx.x;
    float v[4];
    float s = 0.f;
    #pragma unroll
    for (int j = 0; j < 4; j++) { v[j] = A[base + t + j * 256] + R[base + t + j * 256]; s += v[j]; }
    s = blockReduceSum(s);
    float mean = s * (1.f / 1024.f);
    float q = 0.f;
    #pragma unroll
    for (int j = 0; j < 4; j++) { float d = v[j] - mean; q += d * d; }
    q = blockReduceSum(q);
    float sd = sqrtf(q * (1.f / 1023.f));
    #pragma unroll
    for (int j = 0; j < 4; j++) O[base + t + j * 256] = v[j] - mean - sd;
}

// ---------------- host -----------------------------------------------------------------
static const int SMB64  = 4 * (4096 +  64 * 32) * 2;   // 49,152 B -> 3 CTAs/SM
static const int SMB128 = 4 * (4096 + 128 * 32) * 2;   // 65,536 B -> 2 CTAs/SM
static const int PG64   = 456;
static const int PG128  = 304;

extern "C" void kernel_launch(void* const* d_in, const int* in_sizes, int n_in,
                              void* d_out, int out_size) {
    const float* x    = (const float*)d_in[0];
    const float* y    = (const float*)d_in[1];
    const float* Wq1  = (const float*)d_in[2];
    const float* Wk1  = (const float*)d_in[3];
    const float* Wv1  = (const float*)d_in[4];
    const float* Wo1  = (const float*)d_in[5];
    const float* Wq2  = (const float*)d_in[6];
    const float* Wk2  = (const float*)d_in[7];
    const float* Wv2  = (const float*)d_in[8];
    const float* Wo2  = (const float*)d_in[9];
    const float* W_in = (const float*)d_in[10];
    const float* b_in = (const float*)d_in[11];
    const float* W_out= (const float*)d_in[12];
    const float* b_out= (const float*)d_in[13];
    float* out = (float*)d_out;

    __half *xy, *Wt, *WoT, *Win, *Wout, *QKV, *Vt, *S, *P, *hid;
    float *cpart, *dinv, *M, *o1, *o2, *ff;
    cudaGetSymbolAddress((void**)&xy,  g_xy);
    cudaGetSymbolAddress((void**)&Wt,  g_Wt);
    cudaGetSymbolAddress((void**)&WoT, g_WoT);
    cudaGetSymbolAddress((void**)&Win, g_Win);
    cudaGetSymbolAddress((void**)&Wout,g_Wout);
    cudaGetSymbolAddress((void**)&QKV, g_QKV);
    cudaGetSymbolAddress((void**)&Vt,  g_Vt);
    cudaGetSymbolAddress((void**)&S,   g_S);
    cudaGetSymbolAddress((void**)&P,   g_P);
    cudaGetSymbolAddress((void**)&hid, g_hid);
    cudaGetSymbolAddress((void**)&cpart, g_cpart);
    cudaGetSymbolAddress((void**)&dinv,g_dinv);
    cudaGetSymbolAddress((void**)&M,   g_M);
    cudaGetSymbolAddress((void**)&o1,  g_o1);
    cudaGetSymbolAddress((void**)&o2,  g_o2);
    cudaGetSymbolAddress((void**)&ff,  g_ff);

    cudaFuncSetAttribute(mma_multi<64>,  cudaFuncAttributeMaxDynamicSharedMemorySize, SMB64);
    cudaFuncSetAttribute(mma_multi<128>, cudaFuncAttributeMaxDynamicSharedMemorySize, SMB128);

    dim3 blkT(32, 8);
    auto gl64  = [&](int nt) { return dim3((unsigned)(nt < PG64  ? nt : PG64 ), 1, 1); };
    auto gl128 = [&](int nt) { return dim3((unsigned)(nt < PG128 ? nt : PG128), 1, 1); };

    // ---- upfront converts + weight transposes (all independent)
    split_pairs<<<XL/2/256, 256>>>(y, xy,      XL/2);
    split_pairs<<<XL/2/256, 256>>>(x, xy + XL, XL/2);
    split_pairs<<<4*WL/2/256, 256>>>(W_in,  Win,  4*WL/2);
    split_pairs<<<4*WL/2/256, 256>>>(W_out, Wout, 4*WL/2);
    dim3 gw(2, 32, HH);
    transpose_pk<false,false><<<gw, blkT>>>(Wq1, Wt,          nullptr, 1024, 64, 1024, 65536, 0, 1);
    transpose_pk<false,false><<<gw, blkT>>>(Wk1, Wt + WL,     nullptr, 1024, 64, 1024, 65536, 0, 1);
    transpose_pk<false,false><<<gw, blkT>>>(Wv1, Wt + 2 * WL, nullptr, 1024, 64, 1024, 65536, 0, 1);
    transpose_pk<false,false><<<gw, blkT>>>(Wq2, Wt + 3 * WL, nullptr, 1024, 64, 1024, 65536, 0, 1);
    transpose_pk<false,false><<<gw, blkT>>>(Wk2, Wt + 4 * WL, nullptr, 1024, 64, 1024, 65536, 0, 1);
    transpose_pk<false,false><<<gw, blkT>>>(Wv2, Wt + 5 * WL, nullptr, 1024, 64, 1024, 65536, 0, 1);
    dim3 gwo(32, 32, 1);
    transpose_pk<false,false><<<gwo, blkT>>>(Wo1, WoT,      nullptr, 1024, 1024, 1024, 0, 0, 1);
    transpose_pk<false,false><<<gwo, blkT>>>(Wo2, WoT + WL, nullptr, 1024, 1024, 1024, 0, 0, 1);

    auto mk = [&](const __half* A, const __half* B, const float* bias, void* C,
                  float* cp, int K, int lda, int ldb, int ldc,
                  long a1, long a2, long b1, long b2, long c1, long c2,
                  int zdiv, float alpha, int gx, int gy, int flags, int end) {
        GDesc d;
        d.A = A; d.B = B; d.bias = bias; d.C = C; d.cpart = cp;
        d.K = K; d.lda = lda; d.ldb = ldb; d.ldc = ldc;
        d.sA1 = a1; d.sA2 = a2; d.sB1 = b1; d.sB2 = b2; d.sC1 = c1; d.sC2 = c2;
        d.zdiv = zdiv; d.alpha = alpha; d.gx = gx; d.gy = gy;
        d.flags = flags; d.tile_end = end;
        return d;
    };

    const int PACK = 8, EXP = 4, BIAS = 1, RELU = 2, CSUM = 16;

    // MEGA1 (BN=128): QKV1 (768) + QKV2 (768) + FFN1 (1024) = 2560 tiles
    {
        GDesc d0 = mk(xy, Wt, nullptr, QKV, nullptr, 1024, 1024, 1024, 1024,
                      0, 0, 2L*WL, WL, 2L*XL, XL, 2, 1.f, 8, 32, PACK, 768);
        GDesc d1 = mk(xy, Wt + 3*WL, nullptr, QKV + 3*XL, nullptr, 1024, 1024, 1024, 1024,
                      (long)XL, (long)XL, 2L*WL, WL, 2L*XL, XL, 2, 1.f, 8, 32, PACK, 1536);
        GDesc d2 = mk(xy, Win, b_in, hid, nullptr, 1024, 1024, 1024, 4096,
                      0, 0, 0, 0, 0, 0, 1, 1.f, 32, 32, BIAS|RELU|PACK, 2560);
        mma_multi<128><<<gl128(2560), 256, SMB128>>>(d0, d1, d2, 2560);
    }

    // MEGA2 (BN=128): scores1 (4096) + scores2 (4096) + FFN2 (256) = 8448 tiles
    {
        GDesc d0 = mk(QKV, QKV + XL, nullptr, S, cpart, 64, 1024, 1024, 1024,
                      1048576, 64, 1048576, 64, 16777216, 1048576, HH, 0.125f,
                      8, 8, EXP|PACK|CSUM, 4096);
        GDesc d1 = mk(QKV + 3*XL, QKV + 4*XL, nullptr, S + SL, cpart + 524288L,
                      64, 1024, 1024, 1024,
                      1048576, 64, 1048576, 64, 16777216, 1048576, HH, 0.125f,
                      8, 8, EXP|PACK|CSUM, 8192);
        GDesc d2 = mk(hid, Wout, b_out, ff, nullptr, 4096, 4096, 4096, 1024,
                      0, 0, 0, 0, 0, 0, 1, 1.f, 8, 32, BIAS, 8448);
        mma_multi<128><<<gl128(8448), 256, SMB128>>>(d0, d1, d2, 8448);
    }

    // dinv for both MHAs (131072 values)
    inv_partials<<<512, 256>>>(cpart, dinv);

    // Vt transposes (both MHAs)
    dim3 gv(2, 32, BB * HH);
    transpose_pk<true,true><<<gv, blkT>>>(QKV + 2*XL, Vt, dinv,
                                          1024, 1024, 1024, 1048576, 64, HH);
    transpose_pk<true,true><<<gv, blkT>>>(QKV + 5*XL, Vt + XL, dinv + 65536,
                                          1024, 1024, 1024, 1048576, 64, HH);

    // MEGA3 (BN=64): P1 (512) + P2 (512) = 1024 tiles
    {
        GDesc d0 = mk(S, Vt, nullptr, P, nullptr, 1024, 1024, 1024, 1024,
                      16777216, 1048576, 1048576, 65536, 1048576, 64, HH, 1.f,
                      1, 8, PACK, 512);
        GDesc d1 = mk(S + SL, Vt + XL, nullptr, P + XL, nullptr, 1024, 1024, 1024, 1024,
                      16777216, 1048576, 1048576, 65536, 1048576, 64, HH, 1.f,
                      1, 8, PACK, 1024);
        mma_multi<64><<<gl64(1024), 256, SMB64>>>(d0, d1, d1, 1024);
    }

    // MEGA4 (BN=128): Wo1 (256) + Wo2 (256) = 512 tiles
    {
        GDesc d0 = mk(P, WoT, nullptr, M, nullptr, 1024, 1024, 1024, 1024,
                      0, 0, 0, 0, 0, 0, 1, 1.f, 8, 32, 0, 256);
        GDesc d1 = mk(P + XL, WoT + WL, nullptr, M + XL, nullptr, 1024, 1024, 1024, 1024,
                      0, 0, 0, 0, 0, 0, 1, 1.f, 8, 32, 0, 512);
        mma_multi<128><<<gl128(512), 256, SMB128>>>(d0, d1, d1, 512);
    }

    // residual subnorm chain
    add_subnorm<<<BB * TT, 256>>>(M, y, o1);
    add_subnorm<<<BB * TT, 256>>>(M + XL, o1, o2);
    add_subnorm<<<BB * TT, 256>>>(ff, o2, out);
}

// round 15
// speedup vs baseline: 1.5708x; 1.5708x over previous
#include <cuda_runtime.h>
#include <cuda_fp16.h>
#include <math.h>
#include <stdint.h>

#define BB 4
#define TT 1024
#define DD 1024
#define HH 16
#define DKV 64
#define FFD 4096

#define XL   (BB * TT * DD)            // 4,194,304
#define WL   (DD * DD)                 // 1,048,576
#define SL   ((long)BB * HH * TT * TT) // 67,108,864
#define HIDL ((long)BB * TT * FFD)     // 16,777,216

// ---- single-plane fp16 format (RN) -------------------------------------------------
__device__ __align__(16) __half g_xy  [2 * XL];       // y, x
__device__ __align__(16) __half g_Wt  [6 * WL];       // q/k/v weights both MHAs (transposed)
__device__ __align__(16) __half g_WoT [2 * WL];
__device__ __align__(16) __half g_Win [4 * WL];
__device__ __align__(16) __half g_Wout[4 * WL];
__device__ __align__(16) __half g_QKV [6 * XL];       // QKV for both MHAs
__device__ __align__(16) __half g_Vt  [2 * XL];
__device__ __align__(16) __half g_S   [2 * SL];       // 268 MB
__device__ __align__(16) __half g_P   [2 * XL];
__device__ __align__(16) __half g_hid [HIDL];
__device__ float g_cpart[2 * BB * HH * 8 * TT];       // column partials, both MHAs (4MB)
__device__ float g_dinv [2 * BB * HH * TT];
__device__ float g_M [2 * XL];
__device__ float g_o1[XL];
__device__ float g_o2[XL];
__device__ float g_ff[XL];

// ---- GEMM segment descriptor --------------------------------------------------------
// flags: 1=BIAS, 2=RELU, 4=EXP, 8=PACK(fp16 out), 16=CSUM
struct GDesc {
    const __half* A; const __half* B;
    const float* bias; void* C; float* cpart;
    int K, lda, ldb, ldc;
    long sA1, sA2, sB1, sB2, sC1, sC2;
    int zdiv; float alpha; int gx, gy;
    int flags; int tile_end;
};

// ---------------- helpers ----------------
__device__ __forceinline__ void mma_f16(float* c, const uint32_t* a, const uint32_t* b) {
    asm volatile(
        "mma.sync.aligned.m16n8k16.row.col.f32.f16.f16.f32 "
        "{%0,%1,%2,%3}, {%4,%5,%6,%7}, {%8,%9}, {%0,%1,%2,%3};"
        : "+f"(c[0]), "+f"(c[1]), "+f"(c[2]), "+f"(c[3])
        : "r"(a[0]), "r"(a[1]), "r"(a[2]), "r"(a[3]), "r"(b[0]), "r"(b[1]));
}

// ---------------- multi-segment fp16 GEMM (persistent) -------------------------------
// Each tile: 128x64 of alpha * A[M,K] @ B[N,K]^T for its segment's descriptor.
// 8 warps (4x2), warp tile 32x32, 4-stage cp.async (single sync/chunk).
// PACK epilogue stages the fp16 tile in smem (stride-72 rows, conflict-free) and
// emits coalesced STG.128 rows.
__global__ __launch_bounds__(256, 3)
void mma_multi(GDesc D0, GDesc D1, GDesc D2, int ntot)
{
    constexpr int NST = 4;
    constexpr int STGH = 6144;           // halves per stage (A 4096 + B 2048)
    constexpr int OFF_B = 4096;

    extern __shared__ __half smh[];
    uint32_t smb;
    asm("{ .reg .u64 t; cvta.to.shared.u64 t, %1; cvt.u32.u64 %0, t; }" : "=r"(smb) : "l"(smh));

    const int tid  = threadIdx.x;
    const int lane = tid & 31;
    const int wid  = tid >> 5;
    const int wm   = wid >> 1;           // 0..3
    const int wn   = wid & 1;            // 0..1
    const int g    = lane >> 2;
    const int tg   = lane & 3;

    const int ar = wm * 32 + g;
    const int br = wn * 32 + g;

    for (int tile = blockIdx.x; tile < ntot; tile += gridDim.x) {
        const bool in0 = tile < D0.tile_end;
        const bool in1 = tile < D1.tile_end;
        const GDesc d = in0 ? D0 : (in1 ? D1 : D2);
        const int base = in0 ? 0 : (in1 ? D0.tile_end : D1.tile_end);

        const int lt  = tile - base;
        const int z   = lt / (d.gx * d.gy);
        const int rem = lt % (d.gx * d.gy);
        const int trow = rem / d.gx;
        const int row0 = trow * 128;
        const int col0 = (rem % d.gx) * 64;
        const int z1 = z / d.zdiv, z2 = z % d.zdiv;
        const __half* Ahz = d.A + z1 * d.sA1 + z2 * d.sA2;
        const __half* Bhz = d.B + z1 * d.sB1 + z2 * d.sB2;
        const long coff = z1 * d.sC1 + z2 * d.sC2;
        const int lda = d.lda, ldb = d.ldb, ldc = d.ldc;
        const int flags = d.flags;

        float acc[2][4][4];
        #pragma unroll
        for (int i = 0; i < 2; i++)
            #pragma unroll
            for (int j = 0; j < 4; j++)
                #pragma unroll
                for (int q = 0; q < 4; q++) acc[i][j][q] = 0.f;

        const int nch = d.K / 32;

        auto copy_stage = [&](int s, int c) {
            const int kk = c * 32;
            #pragma unroll
            for (int i = tid; i < 768; i += 256) {
                const __half* src;
                uint32_t doff;
                if (i < 512) {
                    int r = i >> 2, q = i & 3;
                    src = Ahz + (long)(row0 + r) * lda + kk + q * 8;
                    doff = (uint32_t)(r * 32 + q * 8);
                } else {
                    int j = i - 512;
                    int r = j >> 2, q = j & 3;
                    src = Bhz + (long)(col0 + r) * ldb + kk + q * 8;
                    doff = (uint32_t)(OFF_B + r * 32 + q * 8);
                }
                uint32_t dst = smb + 2u * ((uint32_t)s * STGH + doff);
                asm volatile("cp.async.cg.shared.global [%0], [%1], 16;" :: "r"(dst), "l"(src));
            }
        };

        // prologue: stages 0..2
        #pragma unroll
        for (int s = 0; s < NST - 1; s++) {
            if (s < nch) copy_stage(s, s);
            asm volatile("cp.async.commit_group;" ::: "memory");
        }

        for (int c = 0; c < nch; c++) {
            // commits issued so far = 3 + c; wait(2) => commits <= c+1 done => chunk c ready
            asm volatile("cp.async.wait_group %0;" :: "n"(NST - 2) : "memory");
            __syncthreads();   // also licenses overwrite of stage (c+3)&3 == (c-1)&3
            if (c + NST - 1 < nch) copy_stage((c + NST - 1) & (NST - 1), c + NST - 1);
            asm volatile("cp.async.commit_group;" ::: "memory");

            const __half* St = smh + (c & (NST - 1)) * STGH;

            uint4 bq[4];
            #pragma unroll
            for (int nt = 0; nt < 4; nt++)
                bq[nt] = *(const uint4*)(St + OFF_B + (br + 8 * nt) * 32 + tg * 8);

            #pragma unroll
            for (int mt = 0; mt < 2; mt++) {
                const __half* arow = St + (ar + 16 * mt) * 32 + tg * 8;
                uint4 h0 = *(const uint4*)(arow);
                uint4 h1 = *(const uint4*)(arow + 8 * 32);
                uint32_t Ah0[4] = {h0.x, h1.x, h0.y, h1.y};
                uint32_t Ah1[4] = {h0.z, h1.z, h0.w, h1.w};
                #pragma unroll
                for (int nt = 0; nt < 4; nt++) {
                    uint32_t b0[2] = {bq[nt].x, bq[nt].y};
                    mma_f16(acc[mt][nt], Ah0, b0);
                }
                #pragma unroll
                for (int nt = 0; nt < 4; nt++) {
                    uint32_t b1[2] = {bq[nt].z, bq[nt].w};
                    mma_f16(acc[mt][nt], Ah1, b1);
                }
            }
        }

        __syncthreads();   // all compute done; smem stages dead -> reusable as epi buffer

        const float alpha = d.alpha;
        float cs[4][2];
        #pragma unroll
        for (int nt = 0; nt < 4; nt++) { cs[nt][0] = 0.f; cs[nt][1] = 0.f; }

        if (flags & 8) {
            // -------- staged fp16 epilogue: STS (stride-72 rows) -> coalesced STG.128
            __half* eb = smh;                       // 128 x 72 halves = 18 KB
            float* colpart = (float*)(smh + 9216);  // 256 floats
            #pragma unroll
            for (int mt = 0; mt < 2; mt++) {
                #pragma unroll
                for (int half_ = 0; half_ < 2; half_++) {
                    const int er = wm * 32 + mt * 16 + half_ * 8 + g;
                    #pragma unroll
                    for (int nt = 0; nt < 4; nt++) {
                        const int ec = wn * 32 + tg * 2 + nt * 8;
                        float v0 = acc[mt][nt][half_ * 2 + 0] * alpha;
                        float v1 = acc[mt][nt][half_ * 2 + 1] * alpha;
                        if (flags & 4)  { v0 = __expf(v0); v1 = __expf(v1); }
                        if (flags & 1)  { v0 += d.bias[col0 + ec]; v1 += d.bias[col0 + ec + 1]; }
                        if (flags & 2)  { v0 = fmaxf(v0, 0.f); v1 = fmaxf(v1, 0.f); }
                        if (flags & 16) { cs[nt][0] += v0; cs[nt][1] += v1; }
                        *(__half2*)(eb + er * 72 + ec) =
                            __halves2half2(__float2half_rn(v0), __float2half_rn(v1));
                    }
                }
            }
            if (flags & 16) {
                #pragma unroll
                for (int nt = 0; nt < 4; nt++) {
                    #pragma unroll
                    for (int p = 0; p < 2; p++) {
                        float v = cs[nt][p];
                        v += __shfl_xor_sync(0xffffffffu, v, 4);
                        v += __shfl_xor_sync(0xffffffffu, v, 8);
                        v += __shfl_xor_sync(0xffffffffu, v, 16);
                        cs[nt][p] = v;
                    }
                }
                if (g == 0) {
                    #pragma unroll
                    for (int nt = 0; nt < 4; nt++) {
                        int lc = wn * 32 + tg * 2 + nt * 8;
                        colpart[wm * 64 + lc]     = cs[nt][0];
                        colpart[wm * 64 + lc + 1] = cs[nt][1];
                    }
                }
            }
            __syncthreads();
            // coalesced copy: 1024 uint4 (128 rows x 8), 4 per thread
            __half* Ch = (__half*)d.C;
            const long crow0 = coff + (long)row0 * ldc + col0;
            #pragma unroll
            for (int k = 0; k < 4; k++) {
                int j = tid + k * 256;
                int r = j >> 3, u = j & 7;
                uint4 v = *(const uint4*)(eb + r * 72 + u * 8);
                *(uint4*)(Ch + crow0 + (long)r * ldc + u * 8) = v;
            }
            if ((flags & 16) && tid < 64) {
                float s4 = colpart[tid] + colpart[64 + tid] +
                           colpart[128 + tid] + colpart[192 + tid];
                d.cpart[(long)z * 8192 + trow * 1024 + col0 + tid] = s4;
            }
        } else {
            // -------- fp32 direct epilogue (M, ff)
            float* Cf = (float*)d.C;
            const int rbase = row0 + wm * 32 + g;
            const int cbase = col0 + wn * 32 + tg * 2;
            #pragma unroll
            for (int mt = 0; mt < 2; mt++) {
                #pragma unroll
                for (int half_ = 0; half_ < 2; half_++) {
                    const long gm = rbase + mt * 16 + half_ * 8;
                    const long rowoff = coff + gm * ldc;
                    #pragma unroll
                    for (int nt = 0; nt < 4; nt++) {
                        const int gn = cbase + nt * 8;
                        float v0 = acc[mt][nt][half_ * 2 + 0] * alpha;
                        float v1 = acc[mt][nt][half_ * 2 + 1] * alpha;
                        if (flags & 1) { v0 += d.bias[gn]; v1 += d.bias[gn + 1]; }
                        float2 o; o.x = v0; o.y = v1;
                        *(float2*)(Cf + rowoff + gn) = o;
                    }
                }
            }
        }
        __syncthreads();   // epilogue buffer / stages safe before next tile's prologue
    }
}

// -------- convert pass: fp32 -> fp16 (RN) --------------------------------------------
__global__ void split_pairs(const float* __restrict__ in, __half* __restrict__ out,
                            int npairs) {
    int i = blockIdx.x * 256 + threadIdx.x;
    if (i >= npairs) return;
    float2 v = *(const float2*)(in + 2 * i);
    *(__half2*)(out + 2 * i) = __halves2half2(__float2half_rn(v.x), __float2half_rn(v.y));
}

// -------- dinv from column partials (both MHAs) --------------------------------------
__global__ void inv_partials(const float* __restrict__ cpart, float* __restrict__ dinv) {
    int i = blockIdx.x * 256 + threadIdx.x;     // 131072 total
    int z = i >> 10, s = i & 1023;
    const float* p = cpart + (long)z * 8192 + s;
    float a = 0.f;
    #pragma unroll
    for (int tr = 0; tr < 8; tr++) a += p[tr * 1024];
    dinv[i] = 1.f / a;
}

// -------- transpose: out[z][c][r] = in[z][r][c] (*scale[z][r]); fp16 out -------------
template<bool SC, bool PIN>
__global__ void transpose_pk(const void* __restrict__ inv, __half* __restrict__ out,
                             const float* __restrict__ scale,
                             int R, int ldin, int ldout,
                             long inS1, long inS2, int zdiv)
{
    __shared__ float tile[32][33];
    const int z = blockIdx.z;
    const long inoff = (long)(z / zdiv) * inS1 + (long)(z % zdiv) * inS2;
    const long outz = (long)z * (long)gridDim.x * 32 * ldout;
    const int c0 = blockIdx.x * 32, r0 = blockIdx.y * 32;
    const int tx = threadIdx.x, ty = threadIdx.y;
    #pragma unroll
    for (int i = ty; i < 32; i += 8) {
        float v;
        long idx = (long)(r0 + i) * ldin + c0 + tx;
        if (PIN) v = __half2float(((const __half*)inv + inoff)[idx]);
        else     v = ((const float*)inv + inoff)[idx];
        if (SC) v *= scale[(long)z * R + r0 + i];
        tile[i][tx] = v;
    }
    __syncthreads();
    #pragma unroll
    for (int i = ty; i < 32; i += 8) {
        long o = outz + (long)(c0 + i) * ldout + r0 + tx;
        out[o] = __float2half_rn(tile[tx][i]);
    }
}

// ---------------- reductions + sub_norm ----------------------------------------------
__device__ __forceinline__ float blockReduceSum(float v) {
    __shared__ float sh[32];
    __syncthreads();
    int lane = threadIdx.x & 31, wid = threadIdx.x >> 5;
    #pragma unroll
    for (int o = 16; o; o >>= 1) v += __shfl_xor_sync(0xffffffffu, v, o);
    if (lane == 0) sh[wid] = v;
    __syncthreads();
    if (wid == 0) {
        v = (threadIdx.x < (blockDim.x >> 5)) ? sh[lane] : 0.f;
        #pragma unroll
        for (int o = 16; o; o >>= 1) v += __shfl_xor_sync(0xffffffffu, v, o);
        if (lane == 0) sh[0] = v;
    }
    __syncthreads();
    return sh[0];
}

__global__ void add_subnorm(const float* __restrict__ A, const float* __restrict__ R,
                            float* __restrict__ O) {
    long base = (long)blockIdx.x * 1024;
    int t = threadIdx.x;
    float v[4];
    float s = 0.f;
    #pragma unroll
    for (int j = 0; j < 4; j++) { v[j] = A[base + t + j * 256] + R[base + t + j * 256]; s += v[j]; }
    s = blockReduceSum(s);
    float mean = s * (1.f / 1024.f);
    float q = 0.f;
    #pragma unroll
    for (int j = 0; j < 4; j++) { float d = v[j] - mean; q += d * d; }
    q = blockReduceSum(q);
    float sd = sqrtf(q * (1.f / 1023.f));
    #pragma unroll
    for (int j = 0; j < 4; j++) O[base + t + j * 256] = v[j] - mean - sd;
}

// ---------------- host -----------------------------------------------------------------
static const int SMB   = 4 * 6144 * 2;    // 49,152 B -> 3 CTAs/SM
static const int PGRID = 456;             // 152 SMs x 3 CTAs

extern "C" void kernel_launch(void* const* d_in, const int* in_sizes, int n_in,
                              void* d_out, int out_size) {
    const float* x    = (const float*)d_in[0];
    const float* y    = (const float*)d_in[1];
    const float* Wq1  = (const float*)d_in[2];
    const float* Wk1  = (const float*)d_in[3];
    const float* Wv1  = (const float*)d_in[4];
    const float* Wo1  = (const float*)d_in[5];
    const float* Wq2  = (const float*)d_in[6];
    const float* Wk2  = (const float*)d_in[7];
    const float* Wv2  = (const float*)d_in[8];
    const float* Wo2  = (const float*)d_in[9];
    const float* W_in = (const float*)d_in[10];
    const float* b_in = (const float*)d_in[11];
    const float* W_out= (const float*)d_in[12];
    const float* b_out= (const float*)d_in[13];
    float* out = (float*)d_out;

    __half *xy, *Wt, *WoT, *Win, *Wout, *QKV, *Vt, *S, *P, *hid;
    float *cpart, *dinv, *M, *o1, *o2, *ff;
    cudaGetSymbolAddress((void**)&xy,  g_xy);
    cudaGetSymbolAddress((void**)&Wt,  g_Wt);
    cudaGetSymbolAddress((void**)&WoT, g_WoT);
    cudaGetSymbolAddress((void**)&Win, g_Win);
    cudaGetSymbolAddress((void**)&Wout,g_Wout);
    cudaGetSymbolAddress((void**)&QKV, g_QKV);
    cudaGetSymbolAddress((void**)&Vt,  g_Vt);
    cudaGetSymbolAddress((void**)&S,   g_S);
    cudaGetSymbolAddress((void**)&P,   g_P);
    cudaGetSymbolAddress((void**)&hid, g_hid);
    cudaGetSymbolAddress((void**)&cpart, g_cpart);
    cudaGetSymbolAddress((void**)&dinv,g_dinv);
    cudaGetSymbolAddress((void**)&M,   g_M);
    cudaGetSymbolAddress((void**)&o1,  g_o1);
    cudaGetSymbolAddress((void**)&o2,  g_o2);
    cudaGetSymbolAddress((void**)&ff,  g_ff);

    cudaFuncSetAttribute(mma_multi, cudaFuncAttributeMaxDynamicSharedMemorySize, SMB);

    dim3 blkT(32, 8);
    auto gl = [&](int nt) { return dim3((unsigned)(nt < PGRID ? nt : PGRID), 1, 1); };

    // ---- upfront converts + weight transposes (all independent)
    split_pairs<<<XL/2/256, 256>>>(y, xy,      XL/2);
    split_pairs<<<XL/2/256, 256>>>(x, xy + XL, XL/2);
    split_pairs<<<4*WL/2/256, 256>>>(W_in,  Win,  4*WL/2);
    split_pairs<<<4*WL/2/256, 256>>>(W_out, Wout, 4*WL/2);
    dim3 gw(2, 32, HH);
    transpose_pk<false,false><<<gw, blkT>>>(Wq1, Wt,          nullptr, 1024, 64, 1024, 65536, 0, 1);
    transpose_pk<false,false><<<gw, blkT>>>(Wk1, Wt + WL,     nullptr, 1024, 64, 1024, 65536, 0, 1);
    transpose_pk<false,false><<<gw, blkT>>>(Wv1, Wt + 2 * WL, nullptr, 1024, 64, 1024, 65536, 0, 1);
    transpose_pk<false,false><<<gw, blkT>>>(Wq2, Wt + 3 * WL, nullptr, 1024, 64, 1024, 65536, 0, 1);
    transpose_pk<false,false><<<gw, blkT>>>(Wk2, Wt + 4 * WL, nullptr, 1024, 64, 1024, 65536, 0, 1);
    transpose_pk<false,false><<<gw, blkT>>>(Wv2, Wt + 5 * WL, nullptr, 1024, 64, 1024, 65536, 0, 1);
    dim3 gwo(32, 32, 1);
    transpose_pk<false,false><<<gwo, blkT>>>(Wo1, WoT,      nullptr, 1024, 1024, 1024, 0, 0, 1);
    transpose_pk<false,false><<<gwo, blkT>>>(Wo2, WoT + WL, nullptr, 1024, 1024, 1024, 0, 0, 1);

    auto mk = [&](const __half* A, const __half* B, const float* bias, void* C,
                  float* cp, int K, int lda, int ldb, int ldc,
                  long a1, long a2, long b1, long b2, long c1, long c2,
                  int zdiv, float alpha, int gx, int gy, int flags, int end) {
        GDesc d;
        d.A = A; d.B = B; d.bias = bias; d.C = C; d.cpart = cp;
        d.K = K; d.lda = lda; d.ldb = ldb; d.ldc = ldc;
        d.sA1 = a1; d.sA2 = a2; d.sB1 = b1; d.sB2 = b2; d.sC1 = c1; d.sC2 = c2;
        d.zdiv = zdiv; d.alpha = alpha; d.gx = gx; d.gy = gy;
        d.flags = flags; d.tile_end = end;
        return d;
    };

    const int PACK = 8, EXP = 4, BIAS = 1, RELU = 2, CSUM = 16;

    // MEGA1: QKV1 (1536) + QKV2 (1536) + FFN1 (2048) = 5120 tiles
    {
        GDesc d0 = mk(xy, Wt, nullptr, QKV, nullptr, 1024, 1024, 1024, 1024,
                      0, 0, 2L*WL, WL, 2L*XL, XL, 2, 1.f, 16, 32, PACK, 1536);
        GDesc d1 = mk(xy, Wt + 3*WL, nullptr, QKV + 3*XL, nullptr, 1024, 1024, 1024, 1024,
                      (long)XL, (long)XL, 2L*WL, WL, 2L*XL, XL, 2, 1.f, 16, 32, PACK, 3072);
        GDesc d2 = mk(xy, Win, b_in, hid, nullptr, 1024, 1024, 1024, 4096,
                      0, 0, 0, 0, 0, 0, 1, 1.f, 64, 32, BIAS|RELU|PACK, 5120);
        mma_multi<<<gl(5120), 256, SMB>>>(d0, d1, d2, 5120);
    }

    // MEGA2: scores1 (8192) + scores2 (8192) + FFN2 (512) = 16896 tiles
    {
        GDesc d0 = mk(QKV, QKV + XL, nullptr, S, cpart, 64, 1024, 1024, 1024,
                      1048576, 64, 1048576, 64, 16777216, 1048576, HH, 0.125f,
                      16, 8, EXP|PACK|CSUM, 8192);
        GDesc d1 = mk(QKV + 3*XL, QKV + 4*XL, nullptr, S + SL, cpart + 524288L,
                      64, 1024, 1024, 1024,
                      1048576, 64, 1048576, 64, 16777216, 1048576, HH, 0.125f,
                      16, 8, EXP|PACK|CSUM, 16384);
        GDesc d2 = mk(hid, Wout, b_out, ff, nullptr, 4096, 4096, 4096, 1024,
                      0, 0, 0, 0, 0, 0, 1, 1.f, 16, 32, BIAS, 16896);
        mma_multi<<<gl(16896), 256, SMB>>>(d0, d1, d2, 16896);
    }

    // dinv for both MHAs (131072 values)
    inv_partials<<<512, 256>>>(cpart, dinv);

    // Vt transposes (both MHAs)
    dim3 gv(2, 32, BB * HH);
    transpose_pk<true,true><<<gv, blkT>>>(QKV + 2*XL, Vt, dinv,
                                          1024, 1024, 1024, 1048576, 64, HH);
    transpose_pk<true,true><<<gv, blkT>>>(QKV + 5*XL, Vt + XL, dinv + 65536,
                                          1024, 1024, 1024, 1048576, 64, HH);

    // MEGA3: P1 (512) + P2 (512) = 1024 tiles
    {
        GDesc d0 = mk(S, Vt, nullptr, P, nullptr, 1024, 1024, 1024, 1024,
                      16777216, 1048576, 1048576, 65536, 1048576, 64, HH, 1.f,
                      1, 8, PACK, 512);
        GDesc d1 = mk(S + SL, Vt + XL, nullptr, P + XL, nullptr, 1024, 1024, 1024, 1024,
                      16777216, 1048576, 1048576, 65536, 1048576, 64, HH, 1.f,
                      1, 8, PACK, 1024);
        mma_multi<<<gl(1024), 256, SMB>>>(d0, d1, d1, 1024);
    }

    // MEGA4: Wo1 (512) + Wo2 (512) = 1024 tiles
    {
        GDesc d0 = mk(P, WoT, nullptr, M, nullptr, 1024, 1024, 1024, 1024,
                      0, 0, 0, 0, 0, 0, 1, 1.f, 16, 32, 0, 512);
        GDesc d1 = mk(P + XL, WoT + WL, nullptr, M + XL, nullptr, 1024, 1024, 1024, 1024,
                      0, 0, 0, 0, 0, 0, 1, 1.f, 16, 32, 0, 1024);
        mma_multi<<<gl(1024), 256, SMB>>>(d0, d1, d1, 1024);
    }

    // residual subnorm chain
    add_subnorm<<<BB * TT, 256>>>(M, y, o1);
    add_subnorm<<<BB * TT, 256>>>(M + XL, o1, o2);
    add_subnorm<<<BB * TT, 256>>>(ff, o2, out);
}

// round 16
// speedup vs baseline: 1.6130x; 1.0269x over previous
#include <cuda_runtime.h>
#include <cuda_fp16.h>
#include <math.h>
#include <stdint.h>

#define BB 4
#define TT 1024
#define DD 1024
#define HH 16
#define DKV 64
#define FFD 4096

#define XL   (BB * TT * DD)            // 4,194,304
#define WL   (DD * DD)                 // 1,048,576
#define SL   ((long)BB * HH * TT * TT) // 67,108,864
#define HIDL ((long)BB * TT * FFD)     // 16,777,216

// ---- single-plane fp16 format (RN) -------------------------------------------------
__device__ __align__(16) __half g_xy  [2 * XL];       // y, x
__device__ __align__(16) __half g_Wt  [6 * WL];       // q/k/v weights both MHAs (transposed)
__device__ __align__(16) __half g_WoT [2 * WL];
__device__ __align__(16) __half g_Win [4 * WL];
__device__ __align__(16) __half g_Wout[4 * WL];
__device__ __align__(16) __half g_QKV [6 * XL];       // QKV for both MHAs
__device__ __align__(16) __half g_Vt  [2 * XL];
__device__ __align__(16) __half g_S   [2 * SL];       // 268 MB
__device__ __align__(16) __half g_P   [2 * XL];
__device__ __align__(16) __half g_hid [HIDL];
__device__ float g_cpart[2 * BB * HH * 8 * TT];       // column partials, both MHAs (4MB)
__device__ float g_dinv [2 * BB * HH * TT];
__device__ float g_M [2 * XL];
__device__ float g_ff[XL];

// ---- GEMM segment descriptor --------------------------------------------------------
// flags: 1=BIAS, 2=RELU, 4=EXP, 8=PACK(fp16 out), 16=CSUM
struct GDesc {
    const __half* A; const __half* B;
    const float* bias; void* C; float* cpart;
    int K, lda, ldb, ldc;
    long sA1, sA2, sB1, sB2, sC1, sC2;
    int zdiv; float alpha; int gx, gy;
    int flags; int tile_end;
};

// ---------------- helpers ----------------
__device__ __forceinline__ void mma_f16(float* c, const uint32_t* a, const uint32_t* b) {
    asm volatile(
        "mma.sync.aligned.m16n8k16.row.col.f32.f16.f16.f32 "
        "{%0,%1,%2,%3}, {%4,%5,%6,%7}, {%8,%9}, {%0,%1,%2,%3};"
        : "+f"(c[0]), "+f"(c[1]), "+f"(c[2]), "+f"(c[3])
        : "r"(a[0]), "r"(a[1]), "r"(a[2]), "r"(a[3]), "r"(b[0]), "r"(b[1]));
}

// ---------------- multi-segment fp16 GEMM (persistent) -------------------------------
// Each tile: 128x64 of alpha * A[M,K] @ B[N,K]^T for its segment's descriptor.
// 8 warps (4x2), warp tile 32x32, 4-stage cp.async (single sync/chunk).
// PACK epilogue stages the fp16 tile in smem (stride-72 rows, conflict-free) and
// emits coalesced STG.128 rows.
__global__ __launch_bounds__(256, 3)
void mma_multi(GDesc D0, GDesc D1, GDesc D2, int ntot)
{
    constexpr int NST = 4;
    constexpr int STGH = 6144;           // halves per stage (A 4096 + B 2048)
    constexpr int OFF_B = 4096;

    extern __shared__ __half smh[];
    uint32_t smb;
    asm("{ .reg .u64 t; cvta.to.shared.u64 t, %1; cvt.u32.u64 %0, t; }" : "=r"(smb) : "l"(smh));

    const int tid  = threadIdx.x;
    const int lane = tid & 31;
    const int wid  = tid >> 5;
    const int wm   = wid >> 1;           // 0..3
    const int wn   = wid & 1;            // 0..1
    const int g    = lane >> 2;
    const int tg   = lane & 3;

    const int ar = wm * 32 + g;
    const int br = wn * 32 + g;

    for (int tile = blockIdx.x; tile < ntot; tile += gridDim.x) {
        const bool in0 = tile < D0.tile_end;
        const bool in1 = tile < D1.tile_end;
        const GDesc d = in0 ? D0 : (in1 ? D1 : D2);
        const int base = in0 ? 0 : (in1 ? D0.tile_end : D1.tile_end);

        const int lt  = tile - base;
        const int z   = lt / (d.gx * d.gy);
        const int rem = lt % (d.gx * d.gy);
        const int trow = rem / d.gx;
        const int row0 = trow * 128;
        const int col0 = (rem % d.gx) * 64;
        const int z1 = z / d.zdiv, z2 = z % d.zdiv;
        const __half* Ahz = d.A + z1 * d.sA1 + z2 * d.sA2;
        const __half* Bhz = d.B + z1 * d.sB1 + z2 * d.sB2;
        const long coff = z1 * d.sC1 + z2 * d.sC2;
        const int lda = d.lda, ldb = d.ldb, ldc = d.ldc;
        const int flags = d.flags;

        float acc[2][4][4];
        #pragma unroll
        for (int i = 0; i < 2; i++)
            #pragma unroll
            for (int j = 0; j < 4; j++)
                #pragma unroll
                for (int q = 0; q < 4; q++) acc[i][j][q] = 0.f;

        const int nch = d.K / 32;

        auto copy_stage = [&](int s, int c) {
            const int kk = c * 32;
            #pragma unroll
            for (int i = tid; i < 768; i += 256) {
                const __half* src;
                uint32_t doff;
                if (i < 512) {
                    int r = i >> 2, q = i & 3;
                    src = Ahz + (long)(row0 + r) * lda + kk + q * 8;
                    doff = (uint32_t)(r * 32 + q * 8);
                } else {
                    int j = i - 512;
                    int r = j >> 2, q = j & 3;
                    src = Bhz + (long)(col0 + r) * ldb + kk + q * 8;
                    doff = (uint32_t)(OFF_B + r * 32 + q * 8);
                }
                uint32_t dst = smb + 2u * ((uint32_t)s * STGH + doff);
                asm volatile("cp.async.cg.shared.global [%0], [%1], 16;" :: "r"(dst), "l"(src));
            }
        };

        // prologue: stages 0..2
        #pragma unroll
        for (int s = 0; s < NST - 1; s++) {
            if (s < nch) copy_stage(s, s);
            asm volatile("cp.async.commit_group;" ::: "memory");
        }

        for (int c = 0; c < nch; c++) {
            // commits issued so far = 3 + c; wait(2) => commits <= c+1 done => chunk c ready
            asm volatile("cp.async.wait_group %0;" :: "n"(NST - 2) : "memory");
            __syncthreads();   // also licenses overwrite of stage (c+3)&3 == (c-1)&3
            if (c + NST - 1 < nch) copy_stage((c + NST - 1) & (NST - 1), c + NST - 1);
            asm volatile("cp.async.commit_group;" ::: "memory");

            const __half* St = smh + (c & (NST - 1)) * STGH;

            uint4 bq[4];
            #pragma unroll
            for (int nt = 0; nt < 4; nt++)
                bq[nt] = *(const uint4*)(St + OFF_B + (br + 8 * nt) * 32 + tg * 8);

            #pragma unroll
            for (int mt = 0; mt < 2; mt++) {
                const __half* arow = St + (ar + 16 * mt) * 32 + tg * 8;
                uint4 h0 = *(const uint4*)(arow);
                uint4 h1 = *(const uint4*)(arow + 8 * 32);
                uint32_t Ah0[4] = {h0.x, h1.x, h0.y, h1.y};
                uint32_t Ah1[4] = {h0.z, h1.z, h0.w, h1.w};
                #pragma unroll
                for (int nt = 0; nt < 4; nt++) {
                    uint32_t b0[2] = {bq[nt].x, bq[nt].y};
                    mma_f16(acc[mt][nt], Ah0, b0);
                }
                #pragma unroll
                for (int nt = 0; nt < 4; nt++) {
                    uint32_t b1[2] = {bq[nt].z, bq[nt].w};
                    mma_f16(acc[mt][nt], Ah1, b1);
                }
            }
        }

        __syncthreads();   // all compute done; smem stages dead -> reusable as epi buffer

        const float alpha = d.alpha;
        float cs[4][2];
        #pragma unroll
        for (int nt = 0; nt < 4; nt++) { cs[nt][0] = 0.f; cs[nt][1] = 0.f; }

        if (flags & 8) {
            // -------- staged fp16 epilogue: STS (stride-72 rows) -> coalesced STG.128
            __half* eb = smh;                       // 128 x 72 halves = 18 KB
            float* colpart = (float*)(smh + 9216);  // 256 floats
            #pragma unroll
            for (int mt = 0; mt < 2; mt++) {
                #pragma unroll
                for (int half_ = 0; half_ < 2; half_++) {
                    const int er = wm * 32 + mt * 16 + half_ * 8 + g;
                    #pragma unroll
                    for (int nt = 0; nt < 4; nt++) {
                        const int ec = wn * 32 + tg * 2 + nt * 8;
                        float v0 = acc[mt][nt][half_ * 2 + 0] * alpha;
                        float v1 = acc[mt][nt][half_ * 2 + 1] * alpha;
                        if (flags & 4)  { v0 = __expf(v0); v1 = __expf(v1); }
                        if (flags & 1)  { v0 += d.bias[col0 + ec]; v1 += d.bias[col0 + ec + 1]; }
                        if (flags & 2)  { v0 = fmaxf(v0, 0.f); v1 = fmaxf(v1, 0.f); }
                        if (flags & 16) { cs[nt][0] += v0; cs[nt][1] += v1; }
                        *(__half2*)(eb + er * 72 + ec) =
                            __halves2half2(__float2half_rn(v0), __float2half_rn(v1));
                    }
                }
            }
            if (flags & 16) {
                #pragma unroll
                for (int nt = 0; nt < 4; nt++) {
                    #pragma unroll
                    for (int p = 0; p < 2; p++) {
                        float v = cs[nt][p];
                        v += __shfl_xor_sync(0xffffffffu, v, 4);
                        v += __shfl_xor_sync(0xffffffffu, v, 8);
                        v += __shfl_xor_sync(0xffffffffu, v, 16);
                        cs[nt][p] = v;
                    }
                }
                if (g == 0) {
                    #pragma unroll
                    for (int nt = 0; nt < 4; nt++) {
                        int lc = wn * 32 + tg * 2 + nt * 8;
                        colpart[wm * 64 + lc]     = cs[nt][0];
                        colpart[wm * 64 + lc + 1] = cs[nt][1];
                    }
                }
            }
            __syncthreads();
            // coalesced copy: 1024 uint4 (128 rows x 8), 4 per thread
            __half* Ch = (__half*)d.C;
            const long crow0 = coff + (long)row0 * ldc + col0;
            #pragma unroll
            for (int k = 0; k < 4; k++) {
                int j = tid + k * 256;
                int r = j >> 3, u = j & 7;
                uint4 v = *(const uint4*)(eb + r * 72 + u * 8);
                *(uint4*)(Ch + crow0 + (long)r * ldc + u * 8) = v;
            }
            if ((flags & 16) && tid < 64) {
                float s4 = colpart[tid] + colpart[64 + tid] +
                           colpart[128 + tid] + colpart[192 + tid];
                d.cpart[(long)z * 8192 + trow * 1024 + col0 + tid] = s4;
            }
        } else {
            // -------- fp32 direct epilogue (M, ff)
            float* Cf = (float*)d.C;
            const int rbase = row0 + wm * 32 + g;
            const int cbase = col0 + wn * 32 + tg * 2;
            #pragma unroll
            for (int mt = 0; mt < 2; mt++) {
                #pragma unroll
                for (int half_ = 0; half_ < 2; half_++) {
                    const long gm = rbase + mt * 16 + half_ * 8;
                    const long rowoff = coff + gm * ldc;
                    #pragma unroll
                    for (int nt = 0; nt < 4; nt++) {
                        const int gn = cbase + nt * 8;
                        float v0 = acc[mt][nt][half_ * 2 + 0] * alpha;
                        float v1 = acc[mt][nt][half_ * 2 + 1] * alpha;
                        if (flags & 1) { v0 += d.bias[gn]; v1 += d.bias[gn + 1]; }
                        float2 o; o.x = v0; o.y = v1;
                        *(float2*)(Cf + rowoff + gn) = o;
                    }
                }
            }
        }
        __syncthreads();   // epilogue buffer / stages safe before next tile's prologue
    }
}

// -------- convert pass: fp32 -> fp16 (RN) --------------------------------------------
__global__ void split_pairs(const float* __restrict__ in, __half* __restrict__ out,
                            int npairs) {
    int i = blockIdx.x * 256 + threadIdx.x;
    if (i >= npairs) return;
    float2 v = *(const float2*)(in + 2 * i);
    *(__half2*)(out + 2 * i) = __halves2half2(__float2half_rn(v.x), __float2half_rn(v.y));
}

// -------- dinv from column partials (both MHAs) --------------------------------------
__global__ void inv_partials(const float* __restrict__ cpart, float* __restrict__ dinv) {
    int i = blockIdx.x * 256 + threadIdx.x;     // 131072 total
    int z = i >> 10, s = i & 1023;
    const float* p = cpart + (long)z * 8192 + s;
    float a = 0.f;
    #pragma unroll
    for (int tr = 0; tr < 8; tr++) a += p[tr * 1024];
    dinv[i] = 1.f / a;
}

// -------- transpose: out[z][c][r] = in[z][r][c] (*scale[z][r]); fp16 out -------------
template<bool SC, bool PIN>
__global__ void transpose_pk(const void* __restrict__ inv, __half* __restrict__ out,
                             const float* __restrict__ scale,
                             int R, int ldin, int ldout,
                             long inS1, long inS2, int zdiv)
{
    __shared__ float tile[32][33];
    const int z = blockIdx.z;
    const long inoff = (long)(z / zdiv) * inS1 + (long)(z % zdiv) * inS2;
    const long outz = (long)z * (long)gridDim.x * 32 * ldout;
    const int c0 = blockIdx.x * 32, r0 = blockIdx.y * 32;
    const int tx = threadIdx.x, ty = threadIdx.y;
    #pragma unroll
    for (int i = ty; i < 32; i += 8) {
        float v;
        long idx = (long)(r0 + i) * ldin + c0 + tx;
        if (PIN) v = __half2float(((const __half*)inv + inoff)[idx]);
        else     v = ((const float*)inv + inoff)[idx];
        if (SC) v *= scale[(long)z * R + r0 + i];
        tile[i][tx] = v;
    }
    __syncthreads();
    #pragma unroll
    for (int i = ty; i < 32; i += 8) {
        long o = outz + (long)(c0 + i) * ldout + r0 + tx;
        out[o] = __float2half_rn(tile[tx][i]);
    }
}

// ---------------- reductions + fused sub_norm chain -----------------------------------
__device__ __forceinline__ float blockReduceSum(float v) {
    __shared__ float sh[32];
    __syncthreads();
    int lane = threadIdx.x & 31, wid = threadIdx.x >> 5;
    #pragma unroll
    for (int o = 16; o; o >>= 1) v += __shfl_xor_sync(0xffffffffu, v, o);
    if (lane == 0) sh[wid] = v;
    __syncthreads();
    if (wid == 0) {
        v = (threadIdx.x < (blockDim.x >> 5)) ? sh[lane] : 0.f;
        #pragma unroll
        for (int o = 16; o; o >>= 1) v += __shfl_xor_sync(0xffffffffu, v, o);
        if (lane == 0) sh[0] = v;
    }
    __syncthreads();
    return sh[0];
}

// one sub_norm stage in registers: v <- (v+add) - mean - std (ddof=1)
__device__ __forceinline__ void subnorm_stage(float* v, const float* __restrict__ add,
                                              long base, int t) {
    float s = 0.f;
    #pragma unroll
    for (int j = 0; j < 4; j++) { v[j] = add[base + t + j * 256] + v[j]; s += v[j]; }
    s = blockReduceSum(s);
    float mean = s * (1.f / 1024.f);
    float q = 0.f;
    #pragma unroll
    for (int j = 0; j < 4; j++) { float d = v[j] - mean; q += d * d; }
    q = blockReduceSum(q);
    float sd = sqrtf(q * (1.f / 1023.f));
    #pragma unroll
    for (int j = 0; j < 4; j++) v[j] = v[j] - mean - sd;
}

// out = sn(ff + sn(M2 + sn(M1 + y)))  -- row stays in registers across all stages
__global__ void subnorm_chain(const float* __restrict__ M1, const float* __restrict__ Y,
                              const float* __restrict__ M2, const float* __restrict__ FFb,
                              float* __restrict__ O) {
    long base = (long)blockIdx.x * 1024;
    int t = threadIdx.x;
    float v[4];
    #pragma unroll
    for (int j = 0; j < 4; j++) v[j] = M1[base + t + j * 256];
    subnorm_stage(v, Y,   base, t);    // o1
    subnorm_stage(v, M2,  base, t);    // wrong order? M2 + o1: add=M2, v=o1 -> v=M2+o1 ✓
    subnorm_stage(v, FFb, base, t);    // ff + o2
    #pragma unroll
    for (int j = 0; j < 4; j++) O[base + t + j * 256] = v[j];
}

// ---------------- host -----------------------------------------------------------------
static const int SMB   = 4 * 6144 * 2;    // 49,152 B -> 3 CTAs/SM
static const int PGRID = 456;             // 152 SMs x 3 CTAs

extern "C" void kernel_launch(void* const* d_in, const int* in_sizes, int n_in,
                              void* d_out, int out_size) {
    const float* x    = (const float*)d_in[0];
    const float* y    = (const float*)d_in[1];
    const float* Wq1  = (const float*)d_in[2];
    const float* Wk1  = (const float*)d_in[3];
    const float* Wv1  = (const float*)d_in[4];
    const float* Wo1  = (const float*)d_in[5];
    const float* Wq2  = (const float*)d_in[6];
    const float* Wk2  = (const float*)d_in[7];
    const float* Wv2  = (const float*)d_in[8];
    const float* Wo2  = (const float*)d_in[9];
    const float* W_in = (const float*)d_in[10];
    const float* b_in = (const float*)d_in[11];
    const float* W_out= (const float*)d_in[12];
    const float* b_out= (const float*)d_in[13];
    float* out = (float*)d_out;

    __half *xy, *Wt, *WoT, *Win, *Wout, *QKV, *Vt, *S, *P, *hid;
    float *cpart, *dinv, *M, *ff;
    cudaGetSymbolAddress((void**)&xy,  g_xy);
    cudaGetSymbolAddress((void**)&Wt,  g_Wt);
    cudaGetSymbolAddress((void**)&WoT, g_WoT);
    cudaGetSymbolAddress((void**)&Win, g_Win);
    cudaGetSymbolAddress((void**)&Wout,g_Wout);
    cudaGetSymbolAddress((void**)&QKV, g_QKV);
    cudaGetSymbolAddress((void**)&Vt,  g_Vt);
    cudaGetSymbolAddress((void**)&S,   g_S);
    cudaGetSymbolAddress((void**)&P,   g_P);
    cudaGetSymbolAddress((void**)&hid, g_hid);
    cudaGetSymbolAddress((void**)&cpart, g_cpart);
    cudaGetSymbolAddress((void**)&dinv,g_dinv);
    cudaGetSymbolAddress((void**)&M,   g_M);
    cudaGetSymbolAddress((void**)&ff,  g_ff);

    cudaFuncSetAttribute(mma_multi, cudaFuncAttributeMaxDynamicSharedMemorySize, SMB);

    dim3 blkT(32, 8);
    auto gl = [&](int nt) { return dim3((unsigned)(nt < PGRID ? nt : PGRID), 1, 1); };

    // ---- upfront converts + weight transposes (all independent)
    split_pairs<<<XL/2/256, 256>>>(y, xy,      XL/2);
    split_pairs<<<XL/2/256, 256>>>(x, xy + XL, XL/2);
    split_pairs<<<4*WL/2/256, 256>>>(W_in,  Win,  4*WL/2);
    split_pairs<<<4*WL/2/256, 256>>>(W_out, Wout, 4*WL/2);
    dim3 gw(2, 32, HH);
    transpose_pk<false,false><<<gw, blkT>>>(Wq1, Wt,          nullptr, 1024, 64, 1024, 65536, 0, 1);
    transpose_pk<false,false><<<gw, blkT>>>(Wk1, Wt + WL,     nullptr, 1024, 64, 1024, 65536, 0, 1);
    transpose_pk<false,false><<<gw, blkT>>>(Wv1, Wt + 2 * WL, nullptr, 1024, 64, 1024, 65536, 0, 1);
    transpose_pk<false,false><<<gw, blkT>>>(Wq2, Wt + 3 * WL, nullptr, 1024, 64, 1024, 65536, 0, 1);
    transpose_pk<false,false><<<gw, blkT>>>(Wk2, Wt + 4 * WL, nullptr, 1024, 64, 1024, 65536, 0, 1);
    transpose_pk<false,false><<<gw, blkT>>>(Wv2, Wt + 5 * WL, nullptr, 1024, 64, 1024, 65536, 0, 1);
    dim3 gwo(32, 32, 1);
    transpose_pk<false,false><<<gwo, blkT>>>(Wo1, WoT,      nullptr, 1024, 1024, 1024, 0, 0, 1);
    transpose_pk<false,false><<<gwo, blkT>>>(Wo2, WoT + WL, nullptr, 1024, 1024, 1024, 0, 0, 1);

    auto mk = [&](const __half* A, const __half* B, const float* bias, void* C,
                  float* cp, int K, int lda, int ldb, int ldc,
                  long a1, long a2, long b1, long b2, long c1, long c2,
                  int zdiv, float alpha, int gx, int gy, int flags, int end) {
        GDesc d;
        d.A = A; d.B = B; d.bias = bias; d.C = C; d.cpart = cp;
        d.K = K; d.lda = lda; d.ldb = ldb; d.ldc = ldc;
        d.sA1 = a1; d.sA2 = a2; d.sB1 = b1; d.sB2 = b2; d.sC1 = c1; d.sC2 = c2;
        d.zdiv = zdiv; d.alpha = alpha; d.gx = gx; d.gy = gy;
        d.flags = flags; d.tile_end = end;
        return d;
    };

    const int PACK = 8, EXP = 4, BIAS = 1, RELU = 2, CSUM = 16;

    // MEGA1: QKV1 (1536) + QKV2 (1536) + FFN1 (2048) = 5120 tiles (uniform K)
    {
        GDesc d0 = mk(xy, Wt, nullptr, QKV, nullptr, 1024, 1024, 1024, 1024,
                      0, 0, 2L*WL, WL, 2L*XL, XL, 2, 1.f, 16, 32, PACK, 1536);
        GDesc d1 = mk(xy, Wt + 3*WL, nullptr, QKV + 3*XL, nullptr, 1024, 1024, 1024, 1024,
                      (long)XL, (long)XL, 2L*WL, WL, 2L*XL, XL, 2, 1.f, 16, 32, PACK, 3072);
        GDesc d2 = mk(xy, Win, b_in, hid, nullptr, 1024, 1024, 1024, 4096,
                      0, 0, 0, 0, 0, 0, 1, 1.f, 64, 32, BIAS|RELU|PACK, 5120);
        mma_multi<<<gl(5120), 256, SMB>>>(d0, d1, d2, 5120);
    }

    // MEGA2: FFN2 FIRST (512 heavy K=4096 tiles drawn in wave 1), then scores1+scores2
    {
        GDesc d0 = mk(hid, Wout, b_out, ff, nullptr, 4096, 4096, 4096, 1024,
                      0, 0, 0, 0, 0, 0, 1, 1.f, 16, 32, BIAS, 512);
        GDesc d1 = mk(QKV, QKV + XL, nullptr, S, cpart, 64, 1024, 1024, 1024,
                      1048576, 64, 1048576, 64, 16777216, 1048576, HH, 0.125f,
                      16, 8, EXP|PACK|CSUM, 8704);
        GDesc d2 = mk(QKV + 3*XL, QKV + 4*XL, nullptr, S + SL, cpart + 524288L,
                      64, 1024, 1024, 1024,
                      1048576, 64, 1048576, 64, 16777216, 1048576, HH, 0.125f,
                      16, 8, EXP|PACK|CSUM, 16896);
        mma_multi<<<gl(16896), 256, SMB>>>(d0, d1, d2, 16896);
    }

    // dinv for both MHAs (131072 values)
    inv_partials<<<512, 256>>>(cpart, dinv);

    // Vt transposes (both MHAs)
    dim3 gv(2, 32, BB * HH);
    transpose_pk<true,true><<<gv, blkT>>>(QKV + 2*XL, Vt, dinv,
                                          1024, 1024, 1024, 1048576, 64, HH);
    transpose_pk<true,true><<<gv, blkT>>>(QKV + 5*XL, Vt + XL, dinv + 65536,
                                          1024, 1024, 1024, 1048576, 64, HH);

    // MEGA3: P1 (512) + P2 (512) = 1024 tiles
    {
        GDesc d0 = mk(S, Vt, nullptr, P, nullptr, 1024, 1024, 1024, 1024,
                      16777216, 1048576, 1048576, 65536, 1048576, 64, HH, 1.f,
                      1, 8, PACK, 512);
        GDesc d1 = mk(S + SL, Vt + XL, nullptr, P + XL, nullptr, 1024, 1024, 1024, 1024,
                      16777216, 1048576, 1048576, 65536, 1048576, 64, HH, 1.f,
                      1, 8, PACK, 1024);
        mma_multi<<<gl(1024), 256, SMB>>>(d0, d1, d1, 1024);
    }

    // MEGA4: Wo1 (512) + Wo2 (512) = 1024 tiles
    {
        GDesc d0 = mk(P, WoT, nullptr, M, nullptr, 1024, 1024, 1024, 1024,
                      0, 0, 0, 0, 0, 0, 1, 1.f, 16, 32, 0, 512);
        GDesc d1 = mk(P + XL, WoT + WL, nullptr, M + XL, nullptr, 1024, 1024, 1024, 1024,
                      0, 0, 0, 0, 0, 0, 1, 1.f, 16, 32, 0, 1024);
        mma_multi<<<gl(1024), 256, SMB>>>(d0, d1, d1, 1024);
    }

    // fused residual subnorm chain: out = sn(ff + sn(M2 + sn(M1 + y)))
    subnorm_chain<<<BB * TT, 256>>>(M, y, M + XL, ff, out);
}